// round 1
// baseline (speedup 1.0000x reference)
#include <cuda_runtime.h>
#include <math.h>
#include <stdint.h>

// Problem constants (fixed by the reference)
#define NN   50000      // nodes
#define FF   64         // node features
#define HH   128        // hidden
#define CLSN 64         // classes
#define EE   800000     // edges
#define ELE  200000     // label edges
#define MPAD 50048      // 782 * 64, padded M so GEMMs need no row guards on scratch
#define KCAT 192        // FF + HH (concatenated GEMM2 K)
#define NG   512        // 4*HH gate width

// ---------------- scratch (device globals: allocation-free, zero-initialized) ----
__device__ float g_deg [MPAD];
__device__ float g_dinv[MPAD];
__device__ float g_xw  [(size_t)MPAD * FF];    // x @ W_gcn (padded rows stay 0)
__device__ float g_agg [(size_t)MPAD * FF];    // GCN aggregation
__device__ float g_abuf[(size_t)MPAD * KCAT];  // [h | hidden1], padded rows stay 0
__device__ float g_B2  [KCAT * NG];            // [Wx ; Th]
__device__ float g_gbuf[(size_t)MPAD * NG];    // gate pre-activations
__device__ float g_hn  [(size_t)MPAD * HH];    // relu(H_new)
__device__ float g_z   [(size_t)MPAD * CLSN];  // softmax output

// ---------------- init: zero agg, deg = 1 (self loop) ---------------------------
__global__ void init_kernel() {
    int i = blockIdx.x * blockDim.x + threadIdx.x;
    if (i < NN * FF) g_agg[i] = 0.0f;
    if (i < NN)      g_deg[i] = 1.0f;
}

// ---------------- degree accumulation -------------------------------------------
__global__ void deg_kernel(const int* __restrict__ dst) {
    int e = blockIdx.x * blockDim.x + threadIdx.x;
    if (e < EE) atomicAdd(&g_deg[dst[e]], 1.0f);
}

__global__ void dinv_kernel() {
    int i = blockIdx.x * blockDim.x + threadIdx.x;
    if (i < NN) g_dinv[i] = rsqrtf(g_deg[i]);   // deg >= 1 always (self loop)
}

// ---------------- tiled fp32 GEMM: C = A @ B (+bias1+bias2) ---------------------
// MODE 0: A=x (input ptr), B=W_gcn (input ptr), C=g_xw, ld=64
// MODE 1: A=g_abuf,        B=g_B2,             C=g_gbuf, ld=512
#define BM 64
#define BN 64
#define BK 16

template<int K, int MODE>
__global__ void __launch_bounds__(256)
sgemm64(const float* __restrict__ Ain, const float* __restrict__ Bin,
        const float* __restrict__ bias1, const float* __restrict__ bias2,
        int Mreal)
{
    constexpr int LD = (MODE == 0) ? 64 : NG;   // ldb == ldc
    const float* A = (MODE == 0) ? Ain : g_abuf;
    const float* B = (MODE == 0) ? Bin : g_B2;
    float*       C = (MODE == 0) ? g_xw : g_gbuf;

    __shared__ float As[BK][BM];
    __shared__ float Bs[BK][BN];

    const int tid = threadIdx.x;
    const int tx = tid & 15, ty = tid >> 4;
    const int rowBase = blockIdx.y * BM;
    const int colBase = blockIdx.x * BN;

    // A-tile load mapping: 64x16 floats, one float4 per thread
    const int ar = tid >> 2;          // 0..63
    const int ac = (tid & 3) * 4;     // 0,4,8,12
    // B-tile load mapping: 16x64 floats, one float4 per thread
    const int br = tid >> 4;          // 0..15
    const int bc = (tid & 15) * 4;    // 0..60

    float acc[4][4] = {};

    for (int k0 = 0; k0 < K; k0 += BK) {
        float4 av = make_float4(0.f, 0.f, 0.f, 0.f);
        int arow = rowBase + ar;
        if (arow < Mreal)
            av = *reinterpret_cast<const float4*>(&A[(size_t)arow * K + k0 + ac]);
        As[ac + 0][ar] = av.x; As[ac + 1][ar] = av.y;
        As[ac + 2][ar] = av.z; As[ac + 3][ar] = av.w;

        float4 bv = *reinterpret_cast<const float4*>(&B[(size_t)(k0 + br) * LD + colBase + bc]);
        *reinterpret_cast<float4*>(&Bs[br][bc]) = bv;
        __syncthreads();

        #pragma unroll
        for (int kk = 0; kk < BK; kk++) {
            float4 a4 = *reinterpret_cast<const float4*>(&As[kk][ty * 4]);
            float4 b4 = *reinterpret_cast<const float4*>(&Bs[kk][tx * 4]);
            float ra[4] = {a4.x, a4.y, a4.z, a4.w};
            float rb[4] = {b4.x, b4.y, b4.z, b4.w};
            #pragma unroll
            for (int i = 0; i < 4; i++)
                #pragma unroll
                for (int j = 0; j < 4; j++)
                    acc[i][j] += ra[i] * rb[j];
        }
        __syncthreads();
    }

    #pragma unroll
    for (int i = 0; i < 4; i++) {
        size_t row = rowBase + ty * 4 + i;          // padded C buffers: no store guard
        float* crow = &C[row * LD + colBase + tx * 4];
        #pragma unroll
        for (int j = 0; j < 4; j++) {
            float v = acc[i][j];
            int col = colBase + tx * 4 + j;
            if (bias1) v += bias1[col];
            if (bias2) v += bias2[col];
            crow[j] = v;
        }
    }
}

// ---------------- GCN scatter: agg[dst] += norm * xw[src], vector atomics -------
__global__ void scatter_kernel(const int* __restrict__ src, const int* __restrict__ dst)
{
    int t = blockIdx.x * blockDim.x + threadIdx.x;
    int e = t >> 4, p = t & 15;
    if (e >= EE) return;
    int s = __ldg(&src[e]);
    int d = __ldg(&dst[e]);
    float norm = __ldg(&g_dinv[s]) * __ldg(&g_dinv[d]);
    float4 v = *reinterpret_cast<const float4*>(&g_xw[(size_t)s * FF + p * 4]);
    v.x *= norm; v.y *= norm; v.z *= norm; v.w *= norm;
    float* ptr = &g_agg[(size_t)d * FF + p * 4];
    asm volatile("red.global.add.v4.f32 [%0], {%1, %2, %3, %4};"
                 :: "l"(ptr), "f"(v.x), "f"(v.y), "f"(v.z), "f"(v.w)
                 : "memory");
}

// ---------------- pack B2 = [Wx ; Th] -------------------------------------------
__global__ void pack_B2(const float* __restrict__ Wx, const float* __restrict__ Th) {
    int i = blockIdx.x * blockDim.x + threadIdx.x;
    if (i < FF * NG)        g_B2[i] = Wx[i];
    else if (i < KCAT * NG) g_B2[i] = Th[i - FF * NG];
}

// ---------------- build A = [h | hidden1], h = agg + dinv^2*xw + b_gcn ----------
__global__ void build_abuf(const float* __restrict__ bgcn, const float* __restrict__ h1) {
    int i = blockIdx.x * blockDim.x + threadIdx.x;
    if (i >= NN * KCAT) return;
    int n = i / KCAT, j = i - n * KCAT;
    float v;
    if (j < FF) {
        float di = g_dinv[n];
        v = g_agg[(size_t)n * FF + j] + di * di * g_xw[(size_t)n * FF + j] + bgcn[j];
    } else {
        v = h1[(size_t)n * HH + (j - FF)];
    }
    g_abuf[i] = v;
}

// ---------------- GCLSTM gates + peephole ---------------------------------------
__device__ __forceinline__ float sigm(float x) { return 1.0f / (1.0f + expf(-x)); }

__global__ void gates_kernel(const float* __restrict__ h2, const float* __restrict__ wc,
                             float* __restrict__ outC)
{
    int i = blockIdx.x * blockDim.x + threadIdx.x;
    if (i >= NN * HH) return;
    int n = i >> 7, j = i & 127;
    const float* g = &g_gbuf[(size_t)n * NG];
    float c2 = h2[i];
    float gi = g[j], gf = g[HH + j], gc = g[2 * HH + j], go = g[3 * HH + j];
    float I  = sigm(gi + wc[j] * c2);
    float Fg = sigm(gf + wc[HH + j] * c2);
    float Cn = Fg * c2 + I * tanhf(gc);
    float O  = sigm(go + wc[2 * HH + j] * Cn);
    float Hn = O * tanhf(Cn);
    outC[i] = Cn;
    g_hn[i] = fmaxf(Hn, 0.0f);
}

// ---------------- Linear + softmax: z = softmax(relu(Hn) @ W_lin + b) -----------
__global__ void __launch_bounds__(256)
lin_softmax(const float* __restrict__ Wl, const float* __restrict__ bl)
{
    __shared__ float sW[HH * CLSN];   // 32 KB
    __shared__ float sb[CLSN];
    __shared__ float sh[8][HH];

    int tid = threadIdx.x;
    for (int i = tid * 4; i < HH * CLSN; i += 256 * 4)
        *reinterpret_cast<float4*>(&sW[i]) = *reinterpret_cast<const float4*>(&Wl[i]);
    if (tid < CLSN) sb[tid] = bl[tid];
    int warp = tid >> 5, lane = tid & 31;
    int n = blockIdx.x * 8 + warp;
    __syncthreads();

    if (n < NN) {
        for (int k = lane; k < HH; k += 32) sh[warp][k] = g_hn[(size_t)n * HH + k];
        __syncwarp();
        float a0 = sb[lane], a1 = sb[lane + 32];
        #pragma unroll 8
        for (int k = 0; k < HH; k++) {
            float hv = sh[warp][k];
            a0 += hv * sW[k * CLSN + lane];
            a1 += hv * sW[k * CLSN + lane + 32];
        }
        float m = fmaxf(a0, a1);
        #pragma unroll
        for (int o = 16; o; o >>= 1) m = fmaxf(m, __shfl_xor_sync(0xFFFFFFFFu, m, o));
        float e0 = expf(a0 - m), e1 = expf(a1 - m);
        float s = e0 + e1;
        #pragma unroll
        for (int o = 16; o; o >>= 1) s += __shfl_xor_sync(0xFFFFFFFFu, s, o);
        float inv = 1.0f / s;
        g_z[(size_t)n * CLSN + lane]      = e0 * inv;
        g_z[(size_t)n * CLSN + lane + 32] = e1 * inv;
    }
}

// ---------------- decode: r[e] = dot(z[src], z[dst]) ----------------------------
__global__ void decode_kernel(const int* __restrict__ s, const int* __restrict__ d,
                              float* __restrict__ r)
{
    int w = (blockIdx.x * blockDim.x + threadIdx.x) >> 5;
    int lane = threadIdx.x & 31;
    if (w >= ELE) return;
    int a = __ldg(&s[w]);
    int b = __ldg(&d[w]);
    float acc = g_z[(size_t)a * CLSN + lane]      * g_z[(size_t)b * CLSN + lane]
              + g_z[(size_t)a * CLSN + lane + 32] * g_z[(size_t)b * CLSN + lane + 32];
    #pragma unroll
    for (int o = 16; o; o >>= 1) acc += __shfl_xor_sync(0xFFFFFFFFu, acc, o);
    if (lane == 0) r[w] = acc;
}

// ---------------- copy hidden1 passthrough into out -----------------------------
__global__ void copy_h1(const float* __restrict__ h1, float* __restrict__ out) {
    int i = blockIdx.x * blockDim.x + threadIdx.x;
    if (i < NN * HH / 4)
        reinterpret_cast<float4*>(out)[i] = reinterpret_cast<const float4*>(h1)[i];
}

// ================================================================================
// Inputs (metadata order):
//  0 x[N,F] f32            1 edge_index[2,E] i32    2 edge_label_index[2,EL] i32
//  3 hidden1[N,H] f32      4 hidden2[N,H] f32       5 W_gcn[F,F]   6 b_gcn[F]
//  7 Wx[F,4H]              8 Th[H,4H]               9 b_gate[4H]  10 b_conv[4H]
// 11 w_c[3,H]             12 W_lin[H,CLS]          13 b_lin[CLS]
// Output: [ r(EL) | hidden1(N*H) | C(N*H) ]  f32
// ================================================================================
extern "C" void kernel_launch(void* const* d_in, const int* in_sizes, int n_in,
                              void* d_out, int out_size)
{
    const float* x    = (const float*)d_in[0];
    const int*   ei   = (const int*)d_in[1];
    const int*   eli  = (const int*)d_in[2];
    const float* h1   = (const float*)d_in[3];
    const float* h2   = (const float*)d_in[4];
    const float* Wgcn = (const float*)d_in[5];
    const float* bgcn = (const float*)d_in[6];
    const float* Wx   = (const float*)d_in[7];
    const float* Th   = (const float*)d_in[8];
    const float* bgate= (const float*)d_in[9];
    const float* bconv= (const float*)d_in[10];
    const float* wc   = (const float*)d_in[11];
    const float* Wlin = (const float*)d_in[12];
    const float* blin = (const float*)d_in[13];

    float* out   = (float*)d_out;
    float* out_r = out;                       // [0, EL)
    float* out_h = out + ELE;                 // [EL, EL + N*H)
    float* out_c = out + ELE + (size_t)NN * HH;

    const int T = 256;

    // 1. init agg=0, deg=1
    init_kernel<<<(NN * FF + T - 1) / T, T>>>();
    // 2. in-degree (+self-loop already in init)
    deg_kernel<<<(EE + T - 1) / T, T>>>(ei + EE);
    // 3. dinv = rsqrt(deg)
    dinv_kernel<<<(NN + T - 1) / T, T>>>();
    // 4. xw = x @ W_gcn  (M guarded at 50000, stores into padded g_xw)
    {
        dim3 grid(FF / BN, MPAD / BM);
        sgemm64<FF, 0><<<grid, 256>>>(x, Wgcn, nullptr, nullptr, NN);
    }
    // 5. scatter: agg[dst] += dinv[src]*dinv[dst]*xw[src]
    scatter_kernel<<<(EE * 16 + T - 1) / T, T>>>(ei, ei + EE);
    // 6. pack B2 = [Wx ; Th]
    pack_B2<<<(KCAT * NG + T - 1) / T, T>>>(Wx, Th);
    // 7. abuf = [agg + dinv^2*xw + b_gcn | hidden1]
    build_abuf<<<(NN * KCAT + T - 1) / T, T>>>(bgcn, h1);
    // 8. gbuf = abuf @ B2 + b_gate + b_conv   (padded M: no guards bind)
    {
        dim3 grid(NG / BN, MPAD / BM);
        sgemm64<KCAT, 1><<<grid, 256>>>(nullptr, nullptr, bgate, bconv, MPAD);
    }
    // 9. gates -> C (to out) and relu(Hn)
    gates_kernel<<<(NN * HH + T - 1) / T, T>>>(h2, wc, out_c);
    // 10. z = softmax(relu(Hn) @ W_lin + b_lin)
    lin_softmax<<<(NN + 7) / 8, 256>>>(Wlin, blin);
    // 11. r = sum(z[src]*z[dst])
    decode_kernel<<<(ELE * 32 + T - 1) / T, T>>>(eli, eli + ELE, out_r);
    // 12. hidden1 passthrough
    copy_h1<<<(NN * HH / 4 + T - 1) / T, T>>>(h1, out_h);
}

// round 2
// speedup vs baseline: 1.5712x; 1.5712x over previous
#include <cuda_runtime.h>
#include <math.h>
#include <stdint.h>

// Problem constants (fixed by the reference)
#define NN   50000      // nodes
#define FF   64         // node features
#define HH   128        // hidden
#define CLSN 64         // classes
#define EE   800000     // edges
#define ELE  200000     // label edges
#define MPAD 50048      // 391 * 128, padded M (no row guards on scratch)
#define KCAT 192        // FF + HH
#define NG   512        // 4*HH

// ---------------- scratch (device globals: allocation-free, zero-initialized) ----
__device__ float g_deg  [MPAD];
__device__ float g_dinv [MPAD];
__device__ float g_xw   [(size_t)MPAD * FF];    // x @ W_gcn
__device__ float g_agg  [(size_t)MPAD * FF];    // GCN aggregation
__device__ float g_abuf [(size_t)MPAD * KCAT];  // [h | hidden1], tf32-rounded
__device__ float g_B2   [KCAT * NG];            // [Wx ; Th], gate-interleaved cols, tf32
__device__ float g_bias2[NG];                   // b_gate + b_conv, gate-interleaved
__device__ float g_hn   [(size_t)MPAD * HH];    // relu(H_new)
__device__ float g_z    [(size_t)MPAD * CLSN];  // softmax output

__device__ __forceinline__ float sigm(float x) { return 1.0f / (1.0f + expf(-x)); }

__device__ __forceinline__ float to_tf32(float x) {
    uint32_t o;
    asm("cvt.rna.tf32.f32 %0, %1;" : "=r"(o) : "f"(x));
    return __uint_as_float(o);
}

// ---------------- init: zero agg, deg = 1 (self loop) ---------------------------
__global__ void init_kernel() {
    int i = blockIdx.x * blockDim.x + threadIdx.x;
    if (i < NN * FF) g_agg[i] = 0.0f;
    if (i < NN)      g_deg[i] = 1.0f;
}

__global__ void deg_kernel(const int* __restrict__ dst) {
    int e = blockIdx.x * blockDim.x + threadIdx.x;
    if (e < EE) atomicAdd(&g_deg[dst[e]], 1.0f);
}

__global__ void dinv_kernel() {
    int i = blockIdx.x * blockDim.x + threadIdx.x;
    if (i < NN) g_dinv[i] = rsqrtf(g_deg[i]);
}

// ---------------- fp32 GEMM1: g_xw = x @ W_gcn (M=NN guarded, K=N=64) ----------
#define BM 64
#define BN 64
#define BK 16

__global__ void __launch_bounds__(256)
sgemm1(const float* __restrict__ A, const float* __restrict__ B)
{
    __shared__ float As[BK][BM];
    __shared__ float Bs[BK][BN];

    const int tid = threadIdx.x;
    const int tx = tid & 15, ty = tid >> 4;
    const int rowBase = blockIdx.y * BM;

    const int ar = tid >> 2;
    const int ac = (tid & 3) * 4;
    const int br = tid >> 4;
    const int bc = (tid & 15) * 4;

    float acc[4][4] = {};

    for (int k0 = 0; k0 < FF; k0 += BK) {
        float4 av = make_float4(0.f, 0.f, 0.f, 0.f);
        int arow = rowBase + ar;
        if (arow < NN)
            av = *reinterpret_cast<const float4*>(&A[(size_t)arow * FF + k0 + ac]);
        As[ac + 0][ar] = av.x; As[ac + 1][ar] = av.y;
        As[ac + 2][ar] = av.z; As[ac + 3][ar] = av.w;

        float4 bv = *reinterpret_cast<const float4*>(&B[(size_t)(k0 + br) * FF + bc]);
        *reinterpret_cast<float4*>(&Bs[br][bc]) = bv;
        __syncthreads();

        #pragma unroll
        for (int kk = 0; kk < BK; kk++) {
            float4 a4 = *reinterpret_cast<const float4*>(&As[kk][ty * 4]);
            float4 b4 = *reinterpret_cast<const float4*>(&Bs[kk][tx * 4]);
            float ra[4] = {a4.x, a4.y, a4.z, a4.w};
            float rb[4] = {b4.x, b4.y, b4.z, b4.w};
            #pragma unroll
            for (int i = 0; i < 4; i++)
                #pragma unroll
                for (int j = 0; j < 4; j++)
                    acc[i][j] += ra[i] * rb[j];
        }
        __syncthreads();
    }

    #pragma unroll
    for (int i = 0; i < 4; i++) {
        size_t row = rowBase + ty * 4 + i;      // padded g_xw: no store guard
        float* crow = &g_xw[row * FF + tx * 4];
        #pragma unroll
        for (int j = 0; j < 4; j++) crow[j] = acc[i][j];
    }
}

// ---------------- GCN scatter: agg[dst] += norm * xw[src], vector atomics -------
__global__ void scatter_kernel(const int* __restrict__ src, const int* __restrict__ dst)
{
    int t = blockIdx.x * blockDim.x + threadIdx.x;
    int e = t >> 4, p = t & 15;
    if (e >= EE) return;
    int s = __ldg(&src[e]);
    int d = __ldg(&dst[e]);
    float norm = __ldg(&g_dinv[s]) * __ldg(&g_dinv[d]);
    float4 v = *reinterpret_cast<const float4*>(&g_xw[(size_t)s * FF + p * 4]);
    v.x *= norm; v.y *= norm; v.z *= norm; v.w *= norm;
    float* ptr = &g_agg[(size_t)d * FF + p * 4];
    asm volatile("red.global.add.v4.f32 [%0], {%1, %2, %3, %4};"
                 :: "l"(ptr), "f"(v.x), "f"(v.y), "f"(v.z), "f"(v.w)
                 : "memory");
}

// ---------------- pack B2: gate-interleaved columns, tf32-rounded ----------------
// new col = 4*j + g  <=>  old col = g*128 + j
__global__ void pack_B2(const float* __restrict__ Wx, const float* __restrict__ Th,
                        const float* __restrict__ bgate, const float* __restrict__ bconv)
{
    int i = blockIdx.x * blockDim.x + threadIdx.x;
    if (i >= KCAT * NG) return;
    int k = i / NG, col = i - k * NG;
    int j = col >> 2, g = col & 3;
    int old = g * HH + j;
    float v = (k < FF) ? Wx[(size_t)k * NG + old] : Th[(size_t)(k - FF) * NG + old];
    g_B2[i] = to_tf32(v);
    if (i < NG) g_bias2[i] = bgate[old] + bconv[old];
}

// ---------------- build A = [h | hidden1] (tf32-rounded) ------------------------
__global__ void build_abuf(const float* __restrict__ bgcn, const float* __restrict__ h1) {
    int i = blockIdx.x * blockDim.x + threadIdx.x;
    if (i >= NN * KCAT) return;
    int n = i / KCAT, j = i - n * KCAT;
    float v;
    if (j < FF) {
        float di = g_dinv[n];
        v = g_agg[(size_t)n * FF + j] + di * di * g_xw[(size_t)n * FF + j] + bgcn[j];
    } else {
        v = h1[(size_t)n * HH + (j - FF)];
    }
    g_abuf[i] = to_tf32(v);
}

// ---------------- tf32 MMA GEMM2 + fused LSTM gate epilogue ---------------------
// C[M=50048, N=512] = abuf @ B2; per 128x64 tile: gates -> outC, g_hn
#define AS_STRIDE 36    // conflict-free A frag reads: bank = (4*gid + tg + c) % 32
#define BS_STRIDE 72    // conflict-free B frag reads: bank = (8*tg + gid + c) % 32
#define CS_STRIDE 68    // float4-aligned epilogue reads

__device__ __forceinline__ void mma8(float* c, const uint32_t* a, const uint32_t* b) {
    asm volatile("mma.sync.aligned.m16n8k8.row.col.f32.tf32.tf32.f32 "
        "{%0,%1,%2,%3}, {%4,%5,%6,%7}, {%8,%9}, {%0,%1,%2,%3};"
        : "+f"(c[0]), "+f"(c[1]), "+f"(c[2]), "+f"(c[3])
        : "r"(a[0]), "r"(a[1]), "r"(a[2]), "r"(a[3]), "r"(b[0]), "r"(b[1]));
}

__global__ void __launch_bounds__(256)
gemm2_gates(const float* __restrict__ h2, const float* __restrict__ wc,
            float* __restrict__ outC)
{
    __shared__ __align__(16) float sm[8704];       // 34.8 KB, aliased
    float* As = sm;                                // [128][36]
    float* Bs = sm + 128 * AS_STRIDE;              // [32][72]
    float* Cs = sm;                                // [128][68] after mma

    const int tid  = threadIdx.x;
    const int lane = tid & 31, warp = tid >> 5;
    const int wm = warp & 3, wn = warp >> 2;       // 4 M-warps x 2 N-warps
    const int gid = lane >> 2, tg = lane & 3;
    const int rowBase = blockIdx.y * 128;
    const int colBase = blockIdx.x * 64;

    float acc[2][4][4];
    #pragma unroll
    for (int mt = 0; mt < 2; mt++)
        #pragma unroll
        for (int nt = 0; nt < 4; nt++)
            #pragma unroll
            for (int r = 0; r < 4; r++) acc[mt][nt][r] = 0.0f;

    for (int kc = 0; kc < KCAT; kc += 32) {
        __syncthreads();
        // stage A: 128 rows x 32 k (1024 float4)
        #pragma unroll
        for (int it = 0; it < 4; it++) {
            int q = tid + it * 256;
            int m = q >> 3, k4 = (q & 7) << 2;
            float4 v = *reinterpret_cast<const float4*>(
                &g_abuf[(size_t)(rowBase + m) * KCAT + kc + k4]);
            *reinterpret_cast<float4*>(&As[m * AS_STRIDE + k4]) = v;
        }
        // stage B: 32 k x 64 n (512 float4)
        #pragma unroll
        for (int it = 0; it < 2; it++) {
            int q = tid + it * 256;
            int k = q >> 4, n4 = (q & 15) << 2;
            float4 v = *reinterpret_cast<const float4*>(
                &g_B2[(size_t)(kc + k) * NG + colBase + n4]);
            *reinterpret_cast<float4*>(&Bs[k * BS_STRIDE + n4]) = v;
        }
        __syncthreads();

        #pragma unroll
        for (int ks = 0; ks < 32; ks += 8) {
            uint32_t a[2][4], b[4][2];
            #pragma unroll
            for (int mt = 0; mt < 2; mt++) {
                int r0 = wm * 32 + mt * 16 + gid;
                a[mt][0] = __float_as_uint(As[r0 * AS_STRIDE + ks + tg]);
                a[mt][1] = __float_as_uint(As[(r0 + 8) * AS_STRIDE + ks + tg]);
                a[mt][2] = __float_as_uint(As[r0 * AS_STRIDE + ks + tg + 4]);
                a[mt][3] = __float_as_uint(As[(r0 + 8) * AS_STRIDE + ks + tg + 4]);
            }
            #pragma unroll
            for (int nt = 0; nt < 4; nt++) {
                int c0 = wn * 32 + nt * 8 + gid;
                b[nt][0] = __float_as_uint(Bs[(ks + tg) * BS_STRIDE + c0]);
                b[nt][1] = __float_as_uint(Bs[(ks + tg + 4) * BS_STRIDE + c0]);
            }
            #pragma unroll
            for (int mt = 0; mt < 2; mt++)
                #pragma unroll
                for (int nt = 0; nt < 4; nt++)
                    mma8(acc[mt][nt], a[mt], b[nt]);
        }
    }

    __syncthreads();
    // spill accumulators to smem for gate-group-contiguous access
    #pragma unroll
    for (int mt = 0; mt < 2; mt++)
        #pragma unroll
        for (int nt = 0; nt < 4; nt++) {
            int r = wm * 32 + mt * 16 + gid;
            int c = wn * 32 + nt * 8 + tg * 2;
            *reinterpret_cast<float2*>(&Cs[r * CS_STRIDE + c]) =
                make_float2(acc[mt][nt][0], acc[mt][nt][1]);
            *reinterpret_cast<float2*>(&Cs[(r + 8) * CS_STRIDE + c]) =
                make_float2(acc[mt][nt][2], acc[mt][nt][3]);
        }
    __syncthreads();

    // fused LSTM gates: 16 hidden units (64 cols) x 128 rows per CTA
    const int j16 = tid & 15;
    const int rl0 = tid >> 4;
    const int jg = (colBase >> 2) + j16;           // global hidden index
    const float w0 = wc[jg], w1 = wc[HH + jg], w2 = wc[2 * HH + jg];
    const float4 bias = *reinterpret_cast<const float4*>(&g_bias2[colBase + j16 * 4]);

    #pragma unroll
    for (int p = 0; p < 8; p++) {
        int rl = p * 16 + rl0;
        int row = rowBase + rl;
        if (row < NN) {
            float4 v = *reinterpret_cast<const float4*>(&Cs[rl * CS_STRIDE + j16 * 4]);
            float c2 = h2[(size_t)row * HH + jg];
            float I  = sigm(v.x + bias.x + w0 * c2);
            float Fg = sigm(v.y + bias.y + w1 * c2);
            float Cn = Fg * c2 + I * tanhf(v.z + bias.z);
            float O  = sigm(v.w + bias.w + w2 * Cn);
            outC[(size_t)row * HH + jg] = Cn;
            g_hn[(size_t)row * HH + jg] = fmaxf(O * tanhf(Cn), 0.0f);
        }
    }
}

// ---------------- Linear + softmax: z = softmax(relu(Hn) @ W_lin + b) -----------
__global__ void __launch_bounds__(256)
lin_softmax(const float* __restrict__ Wl, const float* __restrict__ bl)
{
    __shared__ float sW[HH * CLSN];
    __shared__ float sb[CLSN];
    __shared__ float sh[8][HH];

    int tid = threadIdx.x;
    for (int i = tid * 4; i < HH * CLSN; i += 256 * 4)
        *reinterpret_cast<float4*>(&sW[i]) = *reinterpret_cast<const float4*>(&Wl[i]);
    if (tid < CLSN) sb[tid] = bl[tid];
    int warp = tid >> 5, lane = tid & 31;
    int n = blockIdx.x * 8 + warp;
    __syncthreads();

    if (n < NN) {
        for (int k = lane; k < HH; k += 32) sh[warp][k] = g_hn[(size_t)n * HH + k];
        __syncwarp();
        float a0 = sb[lane], a1 = sb[lane + 32];
        #pragma unroll 8
        for (int k = 0; k < HH; k++) {
            float hv = sh[warp][k];
            a0 += hv * sW[k * CLSN + lane];
            a1 += hv * sW[k * CLSN + lane + 32];
        }
        float m = fmaxf(a0, a1);
        #pragma unroll
        for (int o = 16; o; o >>= 1) m = fmaxf(m, __shfl_xor_sync(0xFFFFFFFFu, m, o));
        float e0 = expf(a0 - m), e1 = expf(a1 - m);
        float s = e0 + e1;
        #pragma unroll
        for (int o = 16; o; o >>= 1) s += __shfl_xor_sync(0xFFFFFFFFu, s, o);
        float inv = 1.0f / s;
        g_z[(size_t)n * CLSN + lane]      = e0 * inv;
        g_z[(size_t)n * CLSN + lane + 32] = e1 * inv;
    }
}

// ---------------- decode: r[e] = dot(z[src], z[dst]) ----------------------------
__global__ void decode_kernel(const int* __restrict__ s, const int* __restrict__ d,
                              float* __restrict__ r)
{
    int w = (blockIdx.x * blockDim.x + threadIdx.x) >> 5;
    int lane = threadIdx.x & 31;
    if (w >= ELE) return;
    int a = __ldg(&s[w]);
    int b = __ldg(&d[w]);
    float acc = g_z[(size_t)a * CLSN + lane]      * g_z[(size_t)b * CLSN + lane]
              + g_z[(size_t)a * CLSN + lane + 32] * g_z[(size_t)b * CLSN + lane + 32];
    #pragma unroll
    for (int o = 16; o; o >>= 1) acc += __shfl_xor_sync(0xFFFFFFFFu, acc, o);
    if (lane == 0) r[w] = acc;
}

// ---------------- copy hidden1 passthrough into out -----------------------------
__global__ void copy_h1(const float* __restrict__ h1, float* __restrict__ out) {
    int i = blockIdx.x * blockDim.x + threadIdx.x;
    if (i < NN * HH / 4)
        reinterpret_cast<float4*>(out)[i] = reinterpret_cast<const float4*>(h1)[i];
}

// ================================================================================
extern "C" void kernel_launch(void* const* d_in, const int* in_sizes, int n_in,
                              void* d_out, int out_size)
{
    const float* x    = (const float*)d_in[0];
    const int*   ei   = (const int*)d_in[1];
    const int*   eli  = (const int*)d_in[2];
    const float* h1   = (const float*)d_in[3];
    const float* h2   = (const float*)d_in[4];
    const float* Wgcn = (const float*)d_in[5];
    const float* bgcn = (const float*)d_in[6];
    const float* Wx   = (const float*)d_in[7];
    const float* Th   = (const float*)d_in[8];
    const float* bgate= (const float*)d_in[9];
    const float* bconv= (const float*)d_in[10];
    const float* wc   = (const float*)d_in[11];
    const float* Wlin = (const float*)d_in[12];
    const float* blin = (const float*)d_in[13];

    float* out   = (float*)d_out;
    float* out_r = out;                       // [0, EL)
    float* out_h = out + ELE;                 // [EL, EL + N*H)
    float* out_c = out + ELE + (size_t)NN * HH;

    const int T = 256;

    init_kernel<<<(NN * FF + T - 1) / T, T>>>();
    deg_kernel<<<(EE + T - 1) / T, T>>>(ei + EE);
    dinv_kernel<<<(NN + T - 1) / T, T>>>();
    {
        dim3 grid(1, MPAD / BM);
        sgemm1<<<grid, 256>>>(x, Wgcn);
    }
    scatter_kernel<<<(EE * 16 + T - 1) / T, T>>>(ei, ei + EE);
    pack_B2<<<(KCAT * NG + T - 1) / T, T>>>(Wx, Th, bgate, bconv);
    build_abuf<<<(NN * KCAT + T - 1) / T, T>>>(bgcn, h1);
    {
        dim3 grid(NG / 64, MPAD / 128);
        gemm2_gates<<<grid, 256>>>(h2, wc, out_c);
    }
    lin_softmax<<<(NN + 7) / 8, 256>>>(Wlin, blin);
    decode_kernel<<<(ELE * 32 + T - 1) / T, T>>>(eli, eli + ELE, out_r);
    copy_h1<<<(NN * HH / 4 + T - 1) / T, T>>>(h1, out_h);
}